// round 1
// baseline (speedup 1.0000x reference)
#include <cuda_runtime.h>
#include <cuda_bf16.h>

#define BB 64
#define TT 512
#define DD 768
#define LL 50

// scratch (no allocs allowed): exp(logits) and per-batch llh
__device__ float g_eem[BB * TT * LL + 64];
__device__ float g_llh[BB];

// ---------- f32x2 helpers (sm_103a packed fp32) ----------
__device__ __forceinline__ unsigned long long pack2(float x, float y) {
    unsigned long long r;
    asm("mov.b64 %0, {%1,%2};" : "=l"(r) : "f"(x), "f"(y));
    return r;
}
__device__ __forceinline__ void unpack2(unsigned long long v, float& x, float& y) {
    asm("mov.b64 {%0,%1}, %2;" : "=f"(x), "=f"(y) : "l"(v));
}
__device__ __forceinline__ void fma2(unsigned long long& d, unsigned long long a,
                                     unsigned long long b) {
    asm("fma.rn.f32x2 %0, %1, %2, %0;" : "+l"(d) : "l"(a), "l"(b));
}
__device__ __forceinline__ float frcp_fast(float x) {
    float r;
    asm("rcp.approx.f32 %0, %1;" : "=f"(r) : "f"(x));
    return r;
}
__device__ __forceinline__ float wred_addf(float x) {
#pragma unroll
    for (int o = 16; o > 0; o >>= 1) x += __shfl_xor_sync(0xffffffffu, x, o);
    return x;
}
__device__ __forceinline__ int wred_addi(int x) {
#pragma unroll
    for (int o = 16; o > 0; o >>= 1) x += __shfl_xor_sync(0xffffffffu, x, o);
    return x;
}

// ---------- GEMM: logits = emb @ W + b ; also eem = exp(logits) ----------
// grid 256 x 128 threads; 1 row per thread; K-tiles of 64.
__global__ void __launch_bounds__(128, 1)
gemm_kernel(const float* __restrict__ A, const float* __restrict__ W,
            const float* __restrict__ bias, float* __restrict__ logits) {
    __shared__ float Ash[64 * 128];              // [kk][row] transposed tile
    __shared__ __align__(16) float Wsh[64 * 52]; // [kk][j] padded to 52
    __shared__ float bsh[52];

    int tid = threadIdx.x;
    int row = blockIdx.x * 128 + tid;
    if (tid < LL) bsh[tid] = bias[tid];

    unsigned long long acc[25];
#pragma unroll
    for (int p = 0; p < 25; p++) acc[p] = 0ull;

    const float4* arow = reinterpret_cast<const float4*>(A + (size_t)row * DD);

    for (int kt = 0; kt < DD / 64; kt++) {
        __syncthreads();
        int k0 = kt * 64;
        // load A tile transposed: Ash[kk][tid]
#pragma unroll
        for (int q = 0; q < 16; q++) {
            float4 f = arow[kt * 16 + q];
            Ash[(q * 4 + 0) * 128 + tid] = f.x;
            Ash[(q * 4 + 1) * 128 + tid] = f.y;
            Ash[(q * 4 + 2) * 128 + tid] = f.z;
            Ash[(q * 4 + 3) * 128 + tid] = f.w;
        }
        // load W chunk [64][50]
        for (int idx = tid; idx < 64 * 50; idx += 128) {
            int kk = idx / 50;
            int j = idx - kk * 50;
            Wsh[kk * 52 + j] = W[(size_t)(k0 + kk) * LL + j];
        }
        __syncthreads();
#pragma unroll 2
        for (int kk = 0; kk < 64; kk++) {
            float a = Ash[kk * 128 + tid];
            unsigned long long ap = pack2(a, a);
            const unsigned long long* wrow =
                reinterpret_cast<const unsigned long long*>(Wsh + kk * 52);
#pragma unroll
            for (int p = 0; p < 25; p++) fma2(acc[p], ap, wrow[p]);
        }
    }
    __syncthreads();
    // stage rows to shared for coalesced stores
    float* st = Ash;
#pragma unroll
    for (int p = 0; p < 25; p++) {
        float x, y;
        unpack2(acc[p], x, y);
        st[tid * 50 + 2 * p] = x + bsh[2 * p];
        st[tid * 50 + 2 * p + 1] = y + bsh[2 * p + 1];
    }
    __syncthreads();
    size_t base = (size_t)blockIdx.x * (128 * 50);
    for (int idx = tid; idx < 128 * 50; idx += 128) {
        float v = st[idx];
        logits[base + idx] = v;
        g_eem[base + idx] = __expf(v);
    }
}

// ---------- mask decode ----------
__device__ __forceinline__ bool mask_on(const void* m, int mode, int idx) {
    if (mode == 0) return ((const int*)m)[idx] != 0;
    if (mode == 1) return ((const unsigned char*)m)[idx] != 0;
    return ((const float*)m)[idx] != 0.0f;
}

// ---------- CRF: one warp per batch ----------
__global__ void __launch_bounds__(32, 1)
crf_kernel(const float* __restrict__ logits, const int* __restrict__ labels,
           const void* __restrict__ maskraw, const float* __restrict__ startT,
           const float* __restrict__ endT, const float* __restrict__ trans) {
    __shared__ float Esh[50 * 80];  // exp(trans)[i][j], row pad 80, zero-padded cols
    __shared__ float trsh[2500];    // raw trans for numerator
    __shared__ float4 pd[2][32];    // double-buffered (p_i,p_i) pairs

    int b = blockIdx.x;
    int u = threadIdx.x;

    // detect mask encoding from first word (mask[0][0]==1, len>=256)
    int mw = *(const int*)maskraw;
    int mode = (mw == 1) ? 0 : ((mw == 0x01010101) ? 1 : 2);

    // sequence length (mask is contiguous prefix)
    int cnt = 0;
    for (int t = u; t < TT; t += 32) cnt += mask_on(maskraw, mode, b * TT + t) ? 1 : 0;
    int len = wred_addi(cnt);

    // init shared
    for (int idx = u; idx < 50 * 80; idx += 32) Esh[idx] = 0.0f;
    __syncwarp();
    for (int idx = u; idx < 2500; idx += 32) {
        float tv = trans[idx];
        trsh[idx] = tv;
        Esh[(idx / 50) * 80 + (idx % 50)] = __expf(tv);
    }
    __syncwarp();

    int j0 = 2 * u, j1 = 2 * u + 1;
    const float* lrow0 = logits + (size_t)b * TT * LL;
    const float* eemb = g_eem + (size_t)b * TT * LL;

    // v = exp(alpha) (scaled); lanes >=25 stay 0
    float vx = 0.0f, vy = 0.0f;
    if (u < 25) {
        vx = __expf(startT[j0] + lrow0[j0]);
        vy = __expf(startT[j1] + lrow0[j1]);
    }
    float S = 0.0f;  // accumulated log-scale
    float2 wv = *(const float2*)(eemb + 1 * LL + j0);  // exp(em) prefetch for t=1

    for (int t = 1; t < len; t++) {
        float v0b = __shfl_sync(0xffffffffu, vx, 0);
        int buf = t & 1;
        pd[buf][u] = make_float4(vx, vx, vy, vy);
        S += __logf(v0b);
        float2 wn = *(const float2*)(eemb + (size_t)(t + 1) * LL + j0);  // prefetch (padded)
        __syncwarp();
        const unsigned long long* pp =
            reinterpret_cast<const unsigned long long*>(&pd[buf][0]);
        const float* Er = Esh + j0;
        unsigned long long a0 = 0ull, a1 = 0ull;
#pragma unroll
        for (int i = 0; i < 50; i += 2) {
            unsigned long long e0 = *reinterpret_cast<const unsigned long long*>(Er + i * 80);
            fma2(a0, pp[i], e0);
            unsigned long long e1 =
                *reinterpret_cast<const unsigned long long*>(Er + (i + 1) * 80);
            fma2(a1, pp[i + 1], e1);
        }
        float d0x, d0y, d1x, d1y;
        unpack2(a0, d0x, d0y);
        unpack2(a1, d1x, d1y);
        float r = frcp_fast(v0b);
        vx = (d0x + d1x) * wv.x * r;
        vy = (d0y + d1y) * wv.y * r;
        wv = wn;
    }

    // denominator: log sum_j v_j * exp(end_j) + S
    float s = 0.0f;
    if (u < 25) s = vx * __expf(endT[j0]) + vy * __expf(endT[j1]);
    float den = __logf(wred_addf(s)) + S;

    // numerator: fully parallel over t (prefix mask => prev = tags[t-1])
    float np = 0.0f;
    const int* lab = labels + b * TT;
    for (int t = u; t < len; t += 32) {
        int tag = lab[t];
        float em = lrow0[(size_t)t * LL + tag];
        if (t == 0)
            np += startT[tag] + em;
        else
            np += trsh[lab[t - 1] * 50 + tag] + em;
        if (t == len - 1) np += endT[tag];
    }
    float num = wred_addf(np);

    if (u == 0) g_llh[b] = num - den;
}

// ---------- final reduce: out[0] = -mean(llh) ----------
__global__ void reduce_kernel(float* __restrict__ out) {
    __shared__ float sh[BB];
    sh[threadIdx.x] = g_llh[threadIdx.x];
    __syncthreads();
    if (threadIdx.x == 0) {
        float s = 0.0f;
        for (int i = 0; i < BB; i++) s += sh[i];
        out[0] = -(s * (1.0f / (float)BB));
    }
}

extern "C" void kernel_launch(void* const* d_in, const int* in_sizes, int n_in,
                              void* d_out, int out_size) {
    (void)in_sizes; (void)n_in; (void)out_size;
    const float* emb    = (const float*)d_in[0];
    const int*   labels = (const int*)d_in[1];
    const void*  mask   = d_in[2];
    const float* W      = (const float*)d_in[3];
    const float* bias   = (const float*)d_in[4];
    const float* startT = (const float*)d_in[5];
    const float* endT   = (const float*)d_in[6];
    const float* trans  = (const float*)d_in[7];

    float* out = (float*)d_out;
    float* logits = out + 1;  // output layout: [ -loss, logits(B*T*L) ]

    gemm_kernel<<<256, 128>>>(emb, W, bias, logits);
    crf_kernel<<<BB, 32>>>(logits, labels, mask, startT, endT, trans);
    reduce_kernel<<<1, BB>>>(out);
}

// round 2
// speedup vs baseline: 1.1662x; 1.1662x over previous
#include <cuda_runtime.h>
#include <cuda_bf16.h>

#define BB 64
#define TT 512
#define DD 768
#define LL 50

// scratch: exp(logits), padded for prefetch overrun (depth-3 => up to +150 elems)
__device__ __align__(16) float g_eem[BB * TT * LL + 256];

// ---------- f32x2 helpers (sm_103a packed fp32) ----------
__device__ __forceinline__ unsigned long long pack2(float x, float y) {
    unsigned long long r;
    asm("mov.b64 %0, {%1,%2};" : "=l"(r) : "f"(x), "f"(y));
    return r;
}
__device__ __forceinline__ void unpack2(unsigned long long v, float& x, float& y) {
    asm("mov.b64 {%0,%1}, %2;" : "=f"(x), "=f"(y) : "l"(v));
}
__device__ __forceinline__ void fma2(unsigned long long& d, unsigned long long a,
                                     unsigned long long b) {
    asm("fma.rn.f32x2 %0, %1, %2, %0;" : "+l"(d) : "l"(a), "l"(b));
}
__device__ __forceinline__ float frcp_fast(float x) {
    float r;
    asm("rcp.approx.f32 %0, %1;" : "=f"(r) : "f"(x));
    return r;
}
__device__ __forceinline__ float wred_addf(float x) {
#pragma unroll
    for (int o = 16; o > 0; o >>= 1) x += __shfl_xor_sync(0xffffffffu, x, o);
    return x;
}
__device__ __forceinline__ int wred_addi(int x) {
#pragma unroll
    for (int o = 16; o > 0; o >>= 1) x += __shfl_xor_sync(0xffffffffu, x, o);
    return x;
}

// ---------- GEMM: logits = emb @ W + b ; eem = exp(logits) ----------
// grid 256 x 128 threads; 1 row/thread; K-tiles of 64; W reads as LDS.128.
#define AP 129
__global__ void __launch_bounds__(128, 3)
gemm_kernel(const float* __restrict__ A, const float* __restrict__ W,
            const float* __restrict__ bias, float* __restrict__ logits,
            float* __restrict__ loss0) {
    __shared__ float Ash[64 * AP];               // [kk][row], pad 129
    __shared__ __align__(16) float Wsh[64 * 52]; // [kk][j], pad to 52 (13 x float4)
    __shared__ float bsh[52];

    int tid = threadIdx.x;
    if (blockIdx.x == 0 && tid == 0) *loss0 = 0.0f;  // zero accumulator for CRF atomics
    if (tid < 52) bsh[tid] = (tid < LL) ? bias[tid] : 0.0f;

    unsigned long long acc[26];
#pragma unroll
    for (int p = 0; p < 26; p++) acc[p] = 0ull;

    const float4* Ag = reinterpret_cast<const float4*>(A);
    int rowbase = blockIdx.x * 128;

    for (int kt = 0; kt < DD / 64; kt++) {
        __syncthreads();
        // coalesced A tile load: lanes 0..15 read 256B contiguous of one row
#pragma unroll
        for (int it = 0; it < 16; it++) {
            int idx = it * 128 + tid;
            int q = idx & 15;
            int r = idx >> 4;
            float4 f = Ag[(size_t)(rowbase + r) * (DD / 4) + kt * 16 + q];
            Ash[(4 * q + 0) * AP + r] = f.x;
            Ash[(4 * q + 1) * AP + r] = f.y;
            Ash[(4 * q + 2) * AP + r] = f.z;
            Ash[(4 * q + 3) * AP + r] = f.w;
        }
        // W chunk [64][50] -> [64][52] zero-padded
        for (int idx = tid; idx < 64 * 52; idx += 128) {
            int kk = idx / 52;
            int j = idx - kk * 52;
            Wsh[idx] = (j < LL) ? W[(size_t)(kt * 64 + kk) * LL + j] : 0.0f;
        }
        __syncthreads();
#pragma unroll 8
        for (int kk = 0; kk < 64; kk++) {
            float a = Ash[kk * AP + tid];
            unsigned long long ap = pack2(a, a);
            const ulonglong2* w2 = reinterpret_cast<const ulonglong2*>(Wsh + kk * 52);
#pragma unroll
            for (int p = 0; p < 13; p++) {
                ulonglong2 w = w2[p];
                fma2(acc[2 * p + 0], ap, w.x);
                fma2(acc[2 * p + 1], ap, w.y);
            }
        }
    }
    __syncthreads();
    // stage for coalesced stores (reuse Ash: need 6400 <= 8256 floats)
    float* st = Ash;
#pragma unroll
    for (int p = 0; p < 25; p++) {
        float x, y;
        unpack2(acc[p], x, y);
        st[tid * 50 + 2 * p + 0] = x + bsh[2 * p + 0];
        st[tid * 50 + 2 * p + 1] = y + bsh[2 * p + 1];
    }
    __syncthreads();
    size_t base = (size_t)blockIdx.x * (128 * LL);
    for (int idx = tid; idx < 128 * LL; idx += 128) {
        float v = st[idx];
        logits[base + idx] = v;
        g_eem[base + idx] = __expf(v);
    }
}

// ---------- mask decode ----------
__device__ __forceinline__ bool mask_on(const void* m, int mode, int idx) {
    if (mode == 0) return ((const int*)m)[idx] != 0;
    if (mode == 1) return ((const unsigned char*)m)[idx] != 0;
    return ((const float*)m)[idx] != 0.0f;
}

// ---------- CRF: one warp per batch; E matrix lives in registers ----------
__global__ void __launch_bounds__(32, 1)
crf_kernel(const float* __restrict__ logits, const int* __restrict__ labels,
           const void* __restrict__ maskraw, const float* __restrict__ startT,
           const float* __restrict__ endT, const float* __restrict__ trans,
           float* __restrict__ loss0) {
    __shared__ unsigned long long pd[2][32];  // double-buffered p-vector pairs
    __shared__ float trsh[2500];              // raw trans for numerator

    int b = blockIdx.x;
    int u = threadIdx.x;

    // detect mask encoding from first word (mask[0][0]==1, len>=256)
    int mw = *(const int*)maskraw;
    int mode = (mw == 1) ? 0 : ((mw == 0x01010101) ? 1 : 2);

    // sequence length (contiguous prefix)
    int cnt = 0;
    for (int t = u; t < TT; t += 32) cnt += mask_on(maskraw, mode, b * TT + t) ? 1 : 0;
    int len = wred_addi(cnt);

    for (int idx = u; idx < 2500; idx += 32) trsh[idx] = trans[idx];
    __syncwarp();

    int j0 = 2 * u, j1 = 2 * u + 1;
    bool act = (u < 25);
    const float* lrow0 = logits + (size_t)b * TT * LL;
    const float* eemb = g_eem + (size_t)b * TT * LL;

    // E in registers: E0[i] = (exp(tr[2i][j0]), exp(tr[2i+1][j0])), E1 for j1
    unsigned long long E0[25], E1[25];
#pragma unroll
    for (int i = 0; i < 25; i++) {
        float a0 = 0.0f, a1 = 0.0f, c0 = 0.0f, c1 = 0.0f;
        if (act) {
            a0 = __expf(trsh[(2 * i) * LL + j0]);
            a1 = __expf(trsh[(2 * i + 1) * LL + j0]);
            c0 = __expf(trsh[(2 * i) * LL + j1]);
            c1 = __expf(trsh[(2 * i + 1) * LL + j1]);
        }
        E0[i] = pack2(a0, a1);
        E1[i] = pack2(c0, c1);
    }

    // v = exp(alpha) scaled; lanes >=25 stay 0
    float vx = 0.0f, vy = 0.0f;
    if (act) {
        vx = __expf(startT[j0] + lrow0[j0]);
        vy = __expf(startT[j1] + lrow0[j1]);
    }
    float S = 0.0f;

    // depth-3 prefetch ring for exp(em)
    unsigned long long w0 = *(const unsigned long long*)(eemb + (size_t)1 * LL + j0);
    unsigned long long w1 = *(const unsigned long long*)(eemb + (size_t)2 * LL + j0);
    unsigned long long w2 = *(const unsigned long long*)(eemb + (size_t)3 * LL + j0);

    for (int t = 1; t < len; t++) {
        float v0b = __shfl_sync(0xffffffffu, vx, 0);
        int buf = t & 1;
        pd[buf][u] = pack2(vx, vy);
        float r = frcp_fast(v0b);
        S += __logf(v0b);
        unsigned long long wn =
            *(const unsigned long long*)(eemb + (size_t)(t + 3) * LL + j0);
        __syncwarp();
        const unsigned long long* pp = pd[buf];
        unsigned long long A00 = 0ull, A01 = 0ull, A10 = 0ull, A11 = 0ull;
#pragma unroll
        for (int i = 0; i < 25; i++) {
            unsigned long long P = pp[i];  // (p_2i, p_2i+1) broadcast
            if (i & 1) {
                fma2(A01, P, E0[i]);
                fma2(A11, P, E1[i]);
            } else {
                fma2(A00, P, E0[i]);
                fma2(A10, P, E1[i]);
            }
        }
        float e0, e1, e2, e3, f0, f1, f2, f3;
        unpack2(A00, e0, e1);
        unpack2(A01, e2, e3);
        unpack2(A10, f0, f1);
        unpack2(A11, f2, f3);
        float s0 = (e0 + e1) + (e2 + e3);
        float s1 = (f0 + f1) + (f2 + f3);
        float wx, wyy;
        unpack2(w0, wx, wyy);
        w0 = w1; w1 = w2; w2 = wn;
        vx = s0 * wx * r;
        vy = s1 * wyy * r;
    }

    // denominator
    float s = 0.0f;
    if (act) s = vx * __expf(endT[j0]) + vy * __expf(endT[j1]);
    float den = __logf(wred_addf(s)) + S;

    // numerator: fully parallel (prefix mask => prev tag = labels[t-1])
    float np = 0.0f;
    const int* lab = labels + b * TT;
    for (int t = u; t < len; t += 32) {
        int tag = lab[t];
        float em = lrow0[(size_t)t * LL + tag];
        if (t == 0)
            np += startT[tag] + em;
        else
            np += trsh[lab[t - 1] * LL + tag] + em;
        if (t == len - 1) np += endT[tag];
    }
    float num = wred_addf(np);

    if (u == 0) atomicAdd(loss0, (den - num) * (1.0f / (float)BB));
}

extern "C" void kernel_launch(void* const* d_in, const int* in_sizes, int n_in,
                              void* d_out, int out_size) {
    (void)in_sizes; (void)n_in; (void)out_size;
    const float* emb    = (const float*)d_in[0];
    const int*   labels = (const int*)d_in[1];
    const void*  mask   = d_in[2];
    const float* W      = (const float*)d_in[3];
    const float* bias   = (const float*)d_in[4];
    const float* startT = (const float*)d_in[5];
    const float* endT   = (const float*)d_in[6];
    const float* trans  = (const float*)d_in[7];

    float* out = (float*)d_out;
    float* logits = out + 1;  // output layout: [ -loss, logits(B*T*L) ]

    gemm_kernel<<<256, 128>>>(emb, W, bias, logits, out);
    crf_kernel<<<BB, 32>>>(logits, labels, mask, startT, endT, trans, out);
}

// round 3
// speedup vs baseline: 1.5230x; 1.3060x over previous
#include <cuda_runtime.h>
#include <cuda_bf16.h>

#define BB 64
#define TT 512
#define DD 768
#define LL 50

typedef unsigned long long ull;

// ---------- f32x2 helpers (sm_103a packed fp32) ----------
__device__ __forceinline__ ull pack2(float x, float y) {
    ull r;
    asm("mov.b64 %0, {%1,%2};" : "=l"(r) : "f"(x), "f"(y));
    return r;
}
__device__ __forceinline__ void unpack2(ull v, float& x, float& y) {
    asm("mov.b64 {%0,%1}, %2;" : "=f"(x), "=f"(y) : "l"(v));
}
__device__ __forceinline__ void fma2(ull& d, ull a, ull b) {
    asm("fma.rn.f32x2 %0, %1, %2, %0;" : "+l"(d) : "l"(a), "l"(b));
}
__device__ __forceinline__ float frcp_fast(float x) {
    float r;
    asm("rcp.approx.f32 %0, %1;" : "=f"(r) : "f"(x));
    return r;
}
__device__ __forceinline__ float wred_addf(float x) {
#pragma unroll
    for (int o = 16; o > 0; o >>= 1) x += __shfl_xor_sync(0xffffffffu, x, o);
    return x;
}
__device__ __forceinline__ int wred_addi(int x) {
#pragma unroll
    for (int o = 16; o > 0; o >>= 1) x += __shfl_xor_sync(0xffffffffu, x, o);
    return x;
}

// ---------- GEMM: logits = emb @ W + b ----------
#define AP 129
__global__ void __launch_bounds__(128, 3)
gemm_kernel(const float* __restrict__ A, const float* __restrict__ W,
            const float* __restrict__ bias, float* __restrict__ logits,
            float* __restrict__ loss0) {
    __shared__ float Ash[64 * AP];               // [kk][row], pad 129
    __shared__ __align__(16) float Wsh[64 * 52]; // [kk][j], pad 52
    __shared__ float bsh[52];

    int tid = threadIdx.x;
    if (blockIdx.x == 0 && tid == 0) *loss0 = 0.0f;
    if (tid < 52) bsh[tid] = (tid < LL) ? bias[tid] : 0.0f;

    ull acc[26];
#pragma unroll
    for (int p = 0; p < 26; p++) acc[p] = 0ull;

    const float4* Ag = reinterpret_cast<const float4*>(A);
    int rowbase = blockIdx.x * 128;

    for (int kt = 0; kt < DD / 64; kt++) {
        __syncthreads();
#pragma unroll
        for (int it = 0; it < 16; it++) {
            int idx = it * 128 + tid;
            int q = idx & 15;
            int r = idx >> 4;
            float4 f = Ag[(size_t)(rowbase + r) * (DD / 4) + kt * 16 + q];
            Ash[(4 * q + 0) * AP + r] = f.x;
            Ash[(4 * q + 1) * AP + r] = f.y;
            Ash[(4 * q + 2) * AP + r] = f.z;
            Ash[(4 * q + 3) * AP + r] = f.w;
        }
        for (int idx = tid; idx < 64 * 52; idx += 128) {
            int kk = idx / 52;
            int j = idx - kk * 52;
            Wsh[idx] = (j < LL) ? W[(size_t)(kt * 64 + kk) * LL + j] : 0.0f;
        }
        __syncthreads();
#pragma unroll 8
        for (int kk = 0; kk < 64; kk++) {
            float a = Ash[kk * AP + tid];
            ull ap = pack2(a, a);
            const ulonglong2* w2 = reinterpret_cast<const ulonglong2*>(Wsh + kk * 52);
#pragma unroll
            for (int p = 0; p < 13; p++) {
                ulonglong2 w = w2[p];
                fma2(acc[2 * p + 0], ap, w.x);
                fma2(acc[2 * p + 1], ap, w.y);
            }
        }
    }
    __syncthreads();
    float* st = Ash;
#pragma unroll
    for (int p = 0; p < 25; p++) {
        float x, y;
        unpack2(acc[p], x, y);
        st[tid * 50 + 2 * p + 0] = x + bsh[2 * p + 0];
        st[tid * 50 + 2 * p + 1] = y + bsh[2 * p + 1];
    }
    __syncthreads();
    size_t base = (size_t)blockIdx.x * (128 * LL);
    for (int idx = tid; idx < 128 * LL; idx += 128)
        logits[base + idx] = st[idx];
}

// ---------- mask decode ----------
__device__ __forceinline__ bool mask_on(const void* m, int mode, int idx) {
    if (mode == 0) return ((const int*)m)[idx] != 0;
    if (mode == 1) return ((const unsigned char*)m)[idx] != 0;
    return ((const float*)m)[idx] != 0.0f;
}

// ---------- CRF: one 128-thread block per batch ----------
// Dynamic smem holds exp(logits) for the whole sequence (100KB).
// Warp 0: forward recurrence (E matrix in registers, p-vector via smem).
// Warp 1: gold-path numerator (fully parallel). Warps 2-3: preload help.
__global__ void __launch_bounds__(128, 1)
crf_kernel(const float* __restrict__ logits, const int* __restrict__ labels,
           const void* __restrict__ maskraw, const float* __restrict__ startT,
           const float* __restrict__ endT, const float* __restrict__ trans,
           float* __restrict__ loss0) {
    extern __shared__ float em[];      // [TT*LL + 128] exp(logits)
    __shared__ float trsh[2500];
    __shared__ ull pd[2][32];
    __shared__ float res_den, res_num;

    int b = blockIdx.x;
    int tid = threadIdx.x;
    int wid = tid >> 5;
    int u = tid & 31;

    const float* lrow0 = logits + (size_t)b * TT * LL;

    // mask encoding + sequence length (contiguous prefix)
    int mw = *(const int*)maskraw;
    int mode = (mw == 1) ? 0 : ((mw == 0x01010101) ? 1 : 2);
    int cnt = 0;
    for (int t = u; t < TT; t += 32) cnt += mask_on(maskraw, mode, b * TT + t) ? 1 : 0;
    int len = wred_addi(cnt);

    // preload exp(logits) into smem (all 128 threads)
    for (int idx = tid; idx < TT * LL; idx += 128) em[idx] = __expf(lrow0[idx]);
    if (tid < 128) em[TT * LL + tid] = 0.0f;  // pad
    for (int idx = tid; idx < 2500; idx += 128) trsh[idx] = trans[idx];
    __syncthreads();

    if (wid == 0) {
        // ---- forward recurrence ----
        int j0 = 2 * u, j1 = 2 * u + 1;
        bool act = (u < 25);
        int j0c = act ? j0 : 0;

        // E in registers: E0[i]=(exp(tr[2i][j0]),exp(tr[2i+1][j0])), E1 for j1
        ull E0[25], E1[25];
#pragma unroll
        for (int i = 0; i < 25; i++) {
            float a0 = 0.0f, a1 = 0.0f, c0 = 0.0f, c1 = 0.0f;
            if (act) {
                a0 = __expf(trsh[(2 * i) * LL + j0]);
                a1 = __expf(trsh[(2 * i + 1) * LL + j0]);
                c0 = __expf(trsh[(2 * i) * LL + j1]);
                c1 = __expf(trsh[(2 * i + 1) * LL + j1]);
            }
            E0[i] = pack2(a0, a1);
            E1[i] = pack2(c0, c1);
        }

        float vx = 0.0f, vy = 0.0f;
        if (act) {
            vx = __expf(startT[j0] + lrow0[j0]);
            vy = __expf(startT[j1] + lrow0[j1]);
        }
        float S = 0.0f;
        float wx = em[1 * LL + j0c];
        float wy = em[1 * LL + j0c + 1];

        for (int t = 1; t < len; t++) {
            float v0b = __shfl_sync(0xffffffffu, vx, 0);
            pd[t & 1][u] = pack2(vx, vy);
            float r = frcp_fast(v0b);
            S += __logf(v0b);
            __syncwarp();
            // prefetch next step's em pair (smem, 29 cyc, off critical path)
            float wnx = em[(t + 1) * LL + j0c];
            float wny = em[(t + 1) * LL + j0c + 1];
            const ull* pp = pd[t & 1];
            ull A00 = 0ull, A01 = 0ull, A10 = 0ull, A11 = 0ull;
#pragma unroll
            for (int i = 0; i < 25; i++) {
                ull P = pp[i];  // broadcast LDS.64
                if (i & 1) {
                    fma2(A01, P, E0[i]);
                    fma2(A11, P, E1[i]);
                } else {
                    fma2(A00, P, E0[i]);
                    fma2(A10, P, E1[i]);
                }
            }
            float e0, e1, e2, e3, f0, f1, f2, f3;
            unpack2(A00, e0, e1);
            unpack2(A01, e2, e3);
            unpack2(A10, f0, f1);
            unpack2(A11, f2, f3);
            float s0 = (e0 + e1) + (e2 + e3);
            float s1 = (f0 + f1) + (f2 + f3);
            vx = s0 * wx * r;
            vy = s1 * wy * r;
            wx = wnx;
            wy = wny;
        }

        float s = 0.0f;
        if (act) s = vx * __expf(endT[j0]) + vy * __expf(endT[j1]);
        float den = __logf(wred_addf(s)) + S;
        if (u == 0) res_den = den;
    } else if (wid == 1) {
        // ---- numerator (parallel; prefix mask => prev tag = labels[t-1]) ----
        float np = 0.0f;
        const int* lab = labels + b * TT;
        for (int t = u; t < len; t += 32) {
            int tag = lab[t];
            float emv = lrow0[(size_t)t * LL + tag];
            if (t == 0)
                np += startT[tag] + emv;
            else
                np += trsh[lab[t - 1] * LL + tag] + emv;
            if (t == len - 1) np += endT[tag];
        }
        float num = wred_addf(np);
        if (u == 0) res_num = num;
    }
    __syncthreads();
    if (tid == 0) atomicAdd(loss0, (res_den - res_num) * (1.0f / (float)BB));
}

extern "C" void kernel_launch(void* const* d_in, const int* in_sizes, int n_in,
                              void* d_out, int out_size) {
    (void)in_sizes; (void)n_in; (void)out_size;
    const float* emb    = (const float*)d_in[0];
    const int*   labels = (const int*)d_in[1];
    const void*  mask   = d_in[2];
    const float* W      = (const float*)d_in[3];
    const float* bias   = (const float*)d_in[4];
    const float* startT = (const float*)d_in[5];
    const float* endT   = (const float*)d_in[6];
    const float* trans  = (const float*)d_in[7];

    float* out = (float*)d_out;
    float* logits = out + 1;  // output layout: [ -loss, logits(B*T*L) ]

    const int dyn = (TT * LL + 128) * sizeof(float);  // 102,912 B
    cudaFuncSetAttribute(crf_kernel, cudaFuncAttributeMaxDynamicSharedMemorySize, dyn);

    gemm_kernel<<<256, 128>>>(emb, W, bias, logits, out);
    crf_kernel<<<BB, 128, dyn>>>(logits, labels, mask, startT, endT, trans, out);
}

// round 4
// speedup vs baseline: 1.6039x; 1.0531x over previous
#include <cuda_runtime.h>
#include <cuda_bf16.h>

#define BB 64
#define TT 512
#define DD 768
#define LL 50

typedef unsigned long long ull;

// ---------- f32x2 helpers (sm_103a packed fp32) ----------
__device__ __forceinline__ ull pack2(float x, float y) {
    ull r;
    asm("mov.b64 %0, {%1,%2};" : "=l"(r) : "f"(x), "f"(y));
    return r;
}
__device__ __forceinline__ void unpack2(ull v, float& x, float& y) {
    asm("mov.b64 {%0,%1}, %2;" : "=f"(x), "=f"(y) : "l"(v));
}
__device__ __forceinline__ void fma2(ull& d, ull a, ull b) {
    asm("fma.rn.f32x2 %0, %1, %2, %0;" : "+l"(d) : "l"(a), "l"(b));
}
__device__ __forceinline__ ull add2(ull a, ull b) {
    ull r;
    asm("add.rn.f32x2 %0, %1, %2;" : "=l"(r) : "l"(a), "l"(b));
    return r;
}
__device__ __forceinline__ float frcp_fast(float x) {
    float r;
    asm("rcp.approx.f32 %0, %1;" : "=f"(r) : "f"(x));
    return r;
}
__device__ __forceinline__ float wred_addf(float x) {
#pragma unroll
    for (int o = 16; o > 0; o >>= 1) x += __shfl_xor_sync(0xffffffffu, x, o);
    return x;
}
__device__ __forceinline__ int wred_addi(int x) {
#pragma unroll
    for (int o = 16; o > 0; o >>= 1) x += __shfl_xor_sync(0xffffffffu, x, o);
    return x;
}

// ---------- GEMM: logits = emb @ W + b ----------
#define AP 129
__global__ void __launch_bounds__(128, 3)
gemm_kernel(const float* __restrict__ A, const float* __restrict__ W,
            const float* __restrict__ bias, float* __restrict__ logits,
            float* __restrict__ loss0) {
    __shared__ float Ash[64 * AP];               // [kk][row], pad 129
    __shared__ __align__(16) float Wsh[64 * 52]; // [kk][j], pad 52
    __shared__ float bsh[52];

    int tid = threadIdx.x;
    if (blockIdx.x == 0 && tid == 0) *loss0 = 0.0f;
    if (tid < 52) bsh[tid] = (tid < LL) ? bias[tid] : 0.0f;

    ull acc[26];
#pragma unroll
    for (int p = 0; p < 26; p++) acc[p] = 0ull;

    const float4* Ag = reinterpret_cast<const float4*>(A);
    int rowbase = blockIdx.x * 128;

    for (int kt = 0; kt < DD / 64; kt++) {
        __syncthreads();
#pragma unroll
        for (int it = 0; it < 16; it++) {
            int idx = it * 128 + tid;
            int q = idx & 15;
            int r = idx >> 4;
            float4 f = Ag[(size_t)(rowbase + r) * (DD / 4) + kt * 16 + q];
            Ash[(4 * q + 0) * AP + r] = f.x;
            Ash[(4 * q + 1) * AP + r] = f.y;
            Ash[(4 * q + 2) * AP + r] = f.z;
            Ash[(4 * q + 3) * AP + r] = f.w;
        }
        for (int idx = tid; idx < 64 * 52; idx += 128) {
            int kk = idx / 52;
            int j = idx - kk * 52;
            Wsh[idx] = (j < LL) ? W[(size_t)(kt * 64 + kk) * LL + j] : 0.0f;
        }
        __syncthreads();
#pragma unroll 8
        for (int kk = 0; kk < 64; kk++) {
            float a = Ash[kk * AP + tid];
            ull ap = pack2(a, a);
            const ulonglong2* w2 = reinterpret_cast<const ulonglong2*>(Wsh + kk * 52);
#pragma unroll
            for (int p = 0; p < 13; p++) {
                ulonglong2 w = w2[p];
                fma2(acc[2 * p + 0], ap, w.x);
                fma2(acc[2 * p + 1], ap, w.y);
            }
        }
    }
    __syncthreads();
    float* st = Ash;
#pragma unroll
    for (int p = 0; p < 25; p++) {
        float x, y;
        unpack2(acc[p], x, y);
        st[tid * 50 + 2 * p + 0] = x + bsh[2 * p + 0];
        st[tid * 50 + 2 * p + 1] = y + bsh[2 * p + 1];
    }
    __syncthreads();
    size_t base = (size_t)blockIdx.x * (128 * LL);
    for (int idx = tid; idx < 128 * LL; idx += 128)
        logits[base + idx] = st[idx];
}

// ---------- mask decode ----------
__device__ __forceinline__ bool mask_on(const void* m, int mode, int idx) {
    if (mode == 0) return ((const int*)m)[idx] != 0;
    if (mode == 1) return ((const unsigned char*)m)[idx] != 0;
    return ((const float*)m)[idx] != 0.0f;
}

// ---------- CRF: one 96-thread block per batch ----------
// Warps 0,1: forward recurrence, ONE output state per lane (j = 25*wid + u).
//   E column in registers, p-vector exchanged via smem + named bar.sync(1,64).
//   Emissions streamed from gmem via depth-4 register ring (unroll 4).
// Warp 2: gold-path numerator (parallel gathers), runs concurrently.
__global__ void __launch_bounds__(96, 1)
crf_kernel(const float* __restrict__ logits, const int* __restrict__ labels,
           const void* __restrict__ maskraw, const float* __restrict__ startT,
           const float* __restrict__ endT, const float* __restrict__ trans,
           float* __restrict__ loss0) {
    __shared__ __align__(16) float pv[2][64];  // double-buffered p-vector
    __shared__ float partial[2];
    __shared__ float res_den, res_num;

    int b = blockIdx.x;
    int tid = threadIdx.x;
    int wid = tid >> 5;
    int u = tid & 31;

    const float* lrow0 = logits + (size_t)b * TT * LL;

    // mask encoding + sequence length (contiguous prefix), per warp
    int mw = *(const int*)maskraw;
    int mode = (mw == 1) ? 0 : ((mw == 0x01010101) ? 1 : 2);
    int cnt = 0;
    for (int t = u; t < TT; t += 32) cnt += mask_on(maskraw, mode, b * TT + t) ? 1 : 0;
    int len = wred_addi(cnt);

    if (wid < 2) {
        // ---- forward recurrence ----
        int j = wid * 25 + u;    // output state
        bool act = (u < 25);
        int jc = act ? j : 0;

        // E column j in registers: E[i] = (exp(tr[2i][j]), exp(tr[2i+1][j]))
        ull E[25];
#pragma unroll
        for (int i = 0; i < 25; i++) {
            float a = 0.0f, c = 0.0f;
            if (act) {
                a = __expf(trans[(2 * i) * LL + j]);
                c = __expf(trans[(2 * i + 1) * LL + j]);
            }
            E[i] = pack2(a, c);
        }

        // initial v(0)
        float v = act ? __expf(startT[j] + lrow0[j]) : 0.0f;
        if (act) pv[0][j] = v;

        // depth-4 logit prefetch ring; slot(t) = (t-1)&3
        float lg[4];
#pragma unroll
        for (int k = 0; k < 4; k++) {
            int tt = 1 + k;
            lg[k] = act ? lrow0[(size_t)tt * LL + j] : 0.0f;
        }

        float S = 0.0f;
        float v0last = 0.0f;  // v0 of final step (for S bookkeeping symmetry)
        (void)v0last;

#pragma unroll 4
        for (int t = 1; t < len; t++) {
            asm volatile("bar.sync 1, 64;" ::: "memory");
            const ull* pp = reinterpret_cast<const ull*>(pv[(t - 1) & 1]);
            ull P0 = pp[0];
            ull a0 = 0ull, a1 = 0ull, a2 = 0ull, a3 = 0ull;
            fma2(a0, P0, E[0]);
#pragma unroll
            for (int i = 1; i < 25; i++) {
                ull P = pp[i];  // broadcast LDS.64
                switch (i & 3) {
                    case 0: fma2(a0, P, E[i]); break;
                    case 1: fma2(a1, P, E[i]); break;
                    case 2: fma2(a2, P, E[i]); break;
                    default: fma2(a3, P, E[i]); break;
                }
            }
            float v0b, dummy;
            unpack2(P0, v0b, dummy);
            float r = frcp_fast(v0b);
            S += __logf(v0b);
            float w = __expf(lg[(t - 1) & 3]);
            ull s01 = add2(a0, a1);
            ull s23 = add2(a2, a3);
            ull sA = add2(s01, s23);
            float sx, sy;
            unpack2(sA, sx, sy);
            v = (sx + sy) * w * r;
            if (act) pv[t & 1][j] = v;
            int tp = t + 4;
            if (tp > TT - 1) tp = TT - 1;
            if (act) lg[(t - 1) & 3] = lrow0[(size_t)tp * LL + j];
        }

        // denominator partials
        float se = act ? v * __expf(endT[j]) : 0.0f;
        float ws = wred_addf(se);
        if (u == 0) partial[wid] = ws;
        asm volatile("bar.sync 1, 64;" ::: "memory");
        if (wid == 0 && u == 0) res_den = __logf(partial[0] + partial[1]) + S;
    } else {
        // ---- numerator (warp 2): prefix mask => prev tag = labels[t-1] ----
        float np = 0.0f;
        const int* lab = labels + b * TT;
#pragma unroll 4
        for (int t = u; t < len; t += 32) {
            int tag = lab[t];
            float emv = lrow0[(size_t)t * LL + tag];
            if (t == 0)
                np += startT[tag] + emv;
            else
                np += trans[lab[t - 1] * LL + tag] + emv;
            if (t == len - 1) np += endT[tag];
        }
        float num = wred_addf(np);
        if (u == 0) res_num = num;
    }
    __syncthreads();
    if (tid == 0) atomicAdd(loss0, (res_den - res_num) * (1.0f / (float)BB));
}

extern "C" void kernel_launch(void* const* d_in, const int* in_sizes, int n_in,
                              void* d_out, int out_size) {
    (void)in_sizes; (void)n_in; (void)out_size;
    const float* emb    = (const float*)d_in[0];
    const int*   labels = (const int*)d_in[1];
    const void*  mask   = d_in[2];
    const float* W      = (const float*)d_in[3];
    const float* bias   = (const float*)d_in[4];
    const float* startT = (const float*)d_in[5];
    const float* endT   = (const float*)d_in[6];
    const float* trans  = (const float*)d_in[7];

    float* out = (float*)d_out;
    float* logits = out + 1;  // output layout: [ -loss, logits(B*T*L) ]

    gemm_kernel<<<256, 128>>>(emb, W, bias, logits, out);
    crf_kernel<<<BB, 96>>>(logits, labels, mask, startT, endT, trans, out);
}